// round 17
// baseline (speedup 1.0000x reference)
#include <cuda_runtime.h>
#include <cuda_bf16.h>
#include <cstdint>

#define NMAX 50000
#define EMAX 600000
#define TEMAX (EMAX + NMAX)

// ---------------- scratch (device globals; no allocation allowed) -------------
__device__ float g_xh1[(size_t)NMAX * 256];
__device__ float g_z1 [(size_t)NMAX * 256];
__device__ float g_xh2[(size_t)NMAX * 64];
__device__ float g_z2 [(size_t)NMAX * 64];
__device__ float g_as1[NMAX * 2];
__device__ float g_ad1[NMAX * 2];
__device__ float g_as2[NMAX];
__device__ float g_ad2[NMAX];
__device__ int   g_counts[NMAX];
__device__ int   g_cursor[NMAX];
__device__ int   g_rowptr[NMAX + 1];
__device__ int   g_esrc[TEMAX];
__device__ int   g_src[EMAX];
__device__ int   g_dst[EMAX];
__device__ int   g_is64;
__device__ int   g_bsums[256];
__device__ int   g_boff[256];

// ---------------- edge dtype detect ------------------------------------------
__global__ void k_detect(const unsigned* __restrict__ w, int nwords) {
    __shared__ int flag;
    if (threadIdx.x == 0) flag = 0;
    __syncthreads();
    for (int i = 1 + 2 * threadIdx.x; i < nwords; i += 2 * blockDim.x)
        if (w[i] != 0u) flag = 1;
    __syncthreads();
    if (threadIdx.x == 0) g_is64 = (flag == 0);
}

// counts start at 1: self-loop folded in
__global__ void k_init_counts(int N) {
    int i = blockIdx.x * blockDim.x + threadIdx.x;
    if (i < N) g_counts[i] = 1;
}

// convert edges to int32 + histogram dst
__global__ void k_cvt_hist(int E, const void* __restrict__ p) {
    int e = blockIdx.x * blockDim.x + threadIdx.x;
    if (e >= E) return;
    int s, d;
    if (g_is64) {
        const long long* q = (const long long*)p;
        s = (int)q[e];
        d = (int)q[E + e];
    } else {
        const int* q = (const int*)p;
        s = q[e];
        d = q[E + e];
    }
    g_src[e] = s;
    g_dst[e] = d;
    atomicAdd(&g_counts[d], 1);
}

// ---------------- parallel scan (3 kernels) -----------------------------------
__global__ void k_bsum(int N) {
    int t = threadIdx.x;
    int i = blockIdx.x * 256 + t;
    int v = (i < N) ? g_counts[i] : 0;
#pragma unroll
    for (int off = 16; off > 0; off >>= 1)
        v += __shfl_down_sync(0xFFFFFFFFu, v, off);
    __shared__ int sh[8];
    if ((t & 31) == 0) sh[t >> 5] = v;
    __syncthreads();
    if (t < 8) {
        int x = sh[t];
#pragma unroll
        for (int off = 4; off > 0; off >>= 1)
            x += __shfl_down_sync(0xFFu, x, off);
        if (t == 0) g_bsums[blockIdx.x] = x;
    }
}

__global__ void k_scan_sums(int nb, int N) {
    __shared__ int sh[256];
    int t = threadIdx.x;
    int v = (t < nb) ? g_bsums[t] : 0;
    sh[t] = v;
    __syncthreads();
#pragma unroll
    for (int off = 1; off < 256; off <<= 1) {
        int x = (t >= off) ? sh[t - off] : 0;
        __syncthreads();
        sh[t] += x;
        __syncthreads();
    }
    if (t < nb) g_boff[t] = sh[t] - v;
    if (t == 255) g_rowptr[N] = sh[255];
}

__global__ void k_scan_apply(int N) {
    __shared__ int sh[256];
    int t = threadIdx.x;
    int i = blockIdx.x * 256 + t;
    int v = (i < N) ? g_counts[i] : 0;
    sh[t] = v;
    __syncthreads();
#pragma unroll
    for (int off = 1; off < 256; off <<= 1) {
        int x = (t >= off) ? sh[t - off] : 0;
        __syncthreads();
        sh[t] += x;
        __syncthreads();
    }
    if (i < N) {
        int excl = sh[t] - v + g_boff[blockIdx.x];
        g_rowptr[i] = excl;
        g_cursor[i] = excl;
    }
}

__global__ void k_scatter(int E, int N) {
    int i = blockIdx.x * blockDim.x + threadIdx.x;
    int TE = E + N;
    if (i >= TE) return;
    int src, dst;
    if (i < E) { src = g_src[i]; dst = g_dst[i]; }
    else       { src = dst = i - E; }
    int pos = atomicAdd(&g_cursor[dst], 1);
    g_esrc[pos] = src;
}

// ---------------- tf32 mma.sync GEMM, cp.async db-buffer, RN at frag read -----
__device__ __forceinline__ uint32_t f2tf(float f) {
    uint32_t u;
    asm("cvt.rna.tf32.f32 %0, %1;" : "=r"(u) : "f"(f));
    return u;
}
__device__ __forceinline__ uint32_t w2tf(uint32_t w) {
    uint32_t u;
    asm("cvt.rna.tf32.f32 %0, %1;" : "=r"(u) : "f"(__uint_as_float(w)));
    return u;
}

__device__ __forceinline__ void mma_tf32(float* c, const uint32_t* a, const uint32_t* b) {
    asm volatile(
        "mma.sync.aligned.m16n8k8.row.col.f32.tf32.tf32.f32 "
        "{%0,%1,%2,%3}, {%4,%5,%6,%7}, {%8,%9}, {%0,%1,%2,%3};"
        : "+f"(c[0]), "+f"(c[1]), "+f"(c[2]), "+f"(c[3])
        : "r"(a[0]), "r"(a[1]), "r"(a[2]), "r"(a[3]), "r"(b[0]), "r"(b[1]));
}

__device__ __forceinline__ void cpa16(void* sdst, const void* gsrc, int srcsize) {
    uint32_t sa = (uint32_t)__cvta_generic_to_shared(sdst);
    asm volatile("cp.async.cg.shared.global [%0], [%1], 16, %2;"
                 :: "r"(sa), "l"(gsrc), "r"(srcsize));
}
__device__ __forceinline__ void cpa_commit() { asm volatile("cp.async.commit_group;"); }
__device__ __forceinline__ void cpa_wait1()  { asm volatile("cp.async.wait_group 1;"); }
__device__ __forceinline__ void cpa_wait0()  { asm volatile("cp.async.wait_group 0;"); }

// C[M,NN] = A[M,K] * B[K,NN]; BM=128 x BN x BK=32; 8 warps (2m x 4n).
// Raw fp32 staged by cp.async; RN tf32 conversion applied at fragment read
// (numerically identical to R12's passing path). Double-buffered.
// Epilogue: fused attention logits.
template<int BN, int K, int NN, int MODE>
__global__ __launch_bounds__(256) void k_mma(int M,
                                             const float* __restrict__ Ain,
                                             const float* __restrict__ B,
                                             const float* __restrict__ att_s,
                                             const float* __restrict__ att_d) {
    const float* __restrict__ A = (MODE == 0) ? Ain : g_z1;
    float* __restrict__ C = (MODE == 0) ? g_xh1 : g_xh2;
    constexpr int NF  = BN / 32;
    constexpr int SZA = 128 * 36;
    constexpr int SZB = 32 * (BN + 8);
    constexpr int NIT = K / 32;

    extern __shared__ uint32_t dsm[];
    uint32_t* AsB = dsm;                     // [2][128][36]
    uint32_t* BsB = dsm + 2 * SZA;           // [2][32][BN+8]
    float* s_part = (float*)(BsB + 2 * SZB); // [4][128][2]

    const int tid  = threadIdx.x;
    const int lane = tid & 31;
    const int wid  = tid >> 5;
    const int g    = lane >> 2;
    const int tg   = lane & 3;
    const int wm   = (wid & 1) * 64;
    const int wn   = (wid >> 1) * (BN / 4);
    const int rowBase = blockIdx.y * 128;
    const int colBase = blockIdx.x * BN;

    float acc[4][NF][4];
#pragma unroll
    for (int i = 0; i < 4; i++)
#pragma unroll
        for (int j = 0; j < NF; j++)
#pragma unroll
            for (int q = 0; q < 4; q++) acc[i][j][q] = 0.f;

    auto stageAB = [&](int s, int k0) {
#pragma unroll
        for (int l = 0; l < 4; l++) {
            int idx = tid + l * 256;
            int r = idx >> 3;             // 0..127
            int c = (idx & 7) * 4;        // 0..28
            int gm = rowBase + r;
            int gmc = (gm < M) ? gm : 0;
            cpa16(&AsB[s * SZA + r * 36 + c],
                  &A[(size_t)gmc * K + k0 + c], (gm < M) ? 16 : 0);
        }
#pragma unroll
        for (int l = 0; l < BN / 32; l++) {
            int idx = tid + l * 256;
            int r = idx / (BN / 4);
            int c = (idx % (BN / 4)) * 4;
            cpa16(&BsB[s * SZB + r * (BN + 8) + c],
                  &B[(size_t)(k0 + r) * NN + colBase + c], 16);
        }
    };

    stageAB(0, 0);
    cpa_commit();

    for (int it = 0; it < NIT; it++) {
        if (it + 1 < NIT) {
            stageAB((it + 1) & 1, (it + 1) * 32);
            cpa_commit();
            cpa_wait1();
        } else {
            cpa_wait0();
        }
        __syncthreads();
        const int s = it & 1;
        const uint32_t* As = AsB + s * SZA;
        const uint32_t* Bs = BsB + s * SZB;
#pragma unroll
        for (int kk = 0; kk < 4; kk++) {
            const int k = kk * 8;
            uint32_t a[4][4];
#pragma unroll
            for (int i = 0; i < 4; i++) {
                int m0 = wm + i * 16;
                a[i][0] = w2tf(As[(m0 + g) * 36 + k + tg]);
                a[i][1] = w2tf(As[(m0 + 8 + g) * 36 + k + tg]);
                a[i][2] = w2tf(As[(m0 + g) * 36 + k + 4 + tg]);
                a[i][3] = w2tf(As[(m0 + 8 + g) * 36 + k + 4 + tg]);
            }
            uint32_t b[NF][2];
#pragma unroll
            for (int j = 0; j < NF; j++) {
                int n0 = wn + j * 8;
                b[j][0] = w2tf(Bs[(k + tg) * (BN + 8) + n0 + g]);
                b[j][1] = w2tf(Bs[(k + 4 + tg) * (BN + 8) + n0 + g]);
            }
#pragma unroll
            for (int i = 0; i < 4; i++)
#pragma unroll
                for (int j = 0; j < NF; j++)
                    mma_tf32(acc[i][j], a[i], b[j]);
        }
        __syncthreads();
    }

    // epilogue: store C + fused attention-logit reduction
    float atsv[NF][2], atdv[NF][2];
#pragma unroll
    for (int j = 0; j < NF; j++) {
        int col = colBase + wn + j * 8 + 2 * tg;
        atsv[j][0] = att_s[col];     atsv[j][1] = att_s[col + 1];
        atdv[j][0] = att_d[col];     atdv[j][1] = att_d[col + 1];
    }

    float rps[8], rpd[8];
#pragma unroll
    for (int i = 0; i < 4; i++) {
        int row0 = rowBase + wm + i * 16 + g;
        int row1 = row0 + 8;
        float ps0 = 0.f, pd0 = 0.f, ps1 = 0.f, pd1 = 0.f;
#pragma unroll
        for (int j = 0; j < NF; j++) {
            ps0 += acc[i][j][0] * atsv[j][0] + acc[i][j][1] * atsv[j][1];
            pd0 += acc[i][j][0] * atdv[j][0] + acc[i][j][1] * atdv[j][1];
            ps1 += acc[i][j][2] * atsv[j][0] + acc[i][j][3] * atsv[j][1];
            pd1 += acc[i][j][2] * atdv[j][0] + acc[i][j][3] * atdv[j][1];
            int col = colBase + wn + j * 8 + 2 * tg;
            if (row0 < M)
                *(float2*)&C[(size_t)row0 * NN + col] = make_float2(acc[i][j][0], acc[i][j][1]);
            if (row1 < M)
                *(float2*)&C[(size_t)row1 * NN + col] = make_float2(acc[i][j][2], acc[i][j][3]);
        }
        rps[2 * i] = ps0; rpd[2 * i] = pd0;
        rps[2 * i + 1] = ps1; rpd[2 * i + 1] = pd1;
    }
#pragma unroll
    for (int q = 0; q < 8; q++) {
        rps[q] += __shfl_xor_sync(0xFFFFFFFFu, rps[q], 1);
        rps[q] += __shfl_xor_sync(0xFFFFFFFFu, rps[q], 2);
        rpd[q] += __shfl_xor_sync(0xFFFFFFFFu, rpd[q], 1);
        rpd[q] += __shfl_xor_sync(0xFFFFFFFFu, rpd[q], 2);
    }
    const int warpN = wid >> 1;
    if (tg == 0) {
#pragma unroll
        for (int i = 0; i < 4; i++) {
            int rl0 = wm + i * 16 + g;
            s_part[(warpN * 128 + rl0) * 2 + 0] = rps[2 * i];
            s_part[(warpN * 128 + rl0) * 2 + 1] = rpd[2 * i];
            s_part[(warpN * 128 + rl0 + 8) * 2 + 0] = rps[2 * i + 1];
            s_part[(warpN * 128 + rl0 + 8) * 2 + 1] = rpd[2 * i + 1];
        }
    }
    __syncthreads();
    if (tid < 128) {
        int row = rowBase + tid;
        if (row < M) {
            float vs = 0.f, vd = 0.f;
#pragma unroll
            for (int w = 0; w < 4; w++) {
                vs += s_part[(w * 128 + tid) * 2 + 0];
                vd += s_part[(w * 128 + tid) * 2 + 1];
            }
            if (MODE == 0) {
                int head = colBase >> 7;
                g_as1[row * 2 + head] = vs;
                g_ad1[row * 2 + head] = vd;
            } else {
                g_as2[row] = vs;
                g_ad2[row] = vd;
            }
        }
    }
}

// ---------------- layer-1 aggregation (H=2, C=128), MLP-batched ---------------
#define CHUNK1 64
__global__ void k_agg1(const float* __restrict__ bias) {
    const float* __restrict__ xh = g_xh1;
    int n = blockIdx.x, t = threadIdx.x;      // t in [0,256)
    int h = t >> 7;
    __shared__ int   ssrc[CHUNK1];
    __shared__ float sw[CHUNK1 * 2];
    int beg = g_rowptr[n], end = g_rowptr[n + 1];
    float acc = 0.f, den = 0.f;
    for (int cs = beg; cs < end; cs += CHUNK1) {
        int m = min(CHUNK1, end - cs);
        if (t < m) ssrc[t] = g_esrc[cs + t];
        __syncthreads();
        if (t < 2 * m) {
            int e = t >> 1, hh = t & 1;
            int s = ssrc[e];
            float ea = g_as1[s * 2 + hh] + g_ad1[n * 2 + hh];
            ea = (ea > 0.f) ? ea : 0.2f * ea;
            sw[e * 2 + hh] = __expf(ea);
        }
        __syncthreads();
        int j = 0;
        for (; j + 4 <= m; j += 4) {
            float w0 = sw[(j + 0) * 2 + h];
            float w1 = sw[(j + 1) * 2 + h];
            float w2 = sw[(j + 2) * 2 + h];
            float w3 = sw[(j + 3) * 2 + h];
            float v0 = xh[(size_t)ssrc[j + 0] * 256 + t];
            float v1 = xh[(size_t)ssrc[j + 1] * 256 + t];
            float v2 = xh[(size_t)ssrc[j + 2] * 256 + t];
            float v3 = xh[(size_t)ssrc[j + 3] * 256 + t];
            acc += w0 * v0; acc += w1 * v1; acc += w2 * v2; acc += w3 * v3;
            den += w0 + w1 + w2 + w3;
        }
        for (; j < m; j++) {
            float w = sw[j * 2 + h];
            acc += w * xh[(size_t)ssrc[j] * 256 + t];
            den += w;
        }
        __syncthreads();
    }
    float z = acc / (den + 1e-16f) + bias[t];
    g_z1[(size_t)n * 256 + t] = fmaxf(z, 0.f);   // fused ReLU
}

// ---------------- layer-2 aggregation (H=1, C=64), MLP-batched ----------------
__global__ void k_agg2(const float* __restrict__ bias) {
    const float* __restrict__ xh = g_xh2;
    int n = blockIdx.x, t = threadIdx.x;      // t in [0,64)
    __shared__ int   ssrc[64];
    __shared__ float sw[64];
    float adh = g_ad2[n];
    int beg = g_rowptr[n], end = g_rowptr[n + 1];
    float acc = 0.f, den = 0.f;
    for (int cs = beg; cs < end; cs += 64) {
        int m = min(64, end - cs);
        if (t < m) {
            int s = g_esrc[cs + t];
            ssrc[t] = s;
            float ea = g_as2[s] + adh;
            ea = (ea > 0.f) ? ea : 0.2f * ea;
            sw[t] = __expf(ea);
        }
        __syncthreads();
        int j = 0;
        for (; j + 4 <= m; j += 4) {
            float w0 = sw[j + 0], w1 = sw[j + 1], w2 = sw[j + 2], w3 = sw[j + 3];
            float v0 = xh[(size_t)ssrc[j + 0] * 64 + t];
            float v1 = xh[(size_t)ssrc[j + 1] * 64 + t];
            float v2 = xh[(size_t)ssrc[j + 2] * 64 + t];
            float v3 = xh[(size_t)ssrc[j + 3] * 64 + t];
            acc += w0 * v0; acc += w1 * v1; acc += w2 * v2; acc += w3 * v3;
            den += w0 + w1 + w2 + w3;
        }
        for (; j < m; j++) {
            float w = sw[j];
            acc += w * xh[(size_t)ssrc[j] * 64 + t];
            den += w;
        }
        __syncthreads();
    }
    g_z2[(size_t)n * 64 + t] = acc / (den + 1e-16f) + bias[t];
}

// ---------------- decode: warp per edge, dot over 64 channels ----------------
__global__ void k_decode(int E, float* __restrict__ out) {
    const float* __restrict__ z = g_z2;
    int gid  = blockIdx.x * blockDim.x + threadIdx.x;
    int warp = gid >> 5;
    int lane = gid & 31;
    if (warp >= E) return;
    int s = g_src[warp];
    int d = g_dst[warp];
    const float* zs = z + (size_t)s * 64;
    const float* zd = z + (size_t)d * 64;
    float v = zs[lane] * zd[lane] + zs[lane + 32] * zd[lane + 32];
#pragma unroll
    for (int off = 16; off > 0; off >>= 1)
        v += __shfl_down_sync(0xFFFFFFFFu, v, off);
    if (lane == 0) out[warp] = v;
}

// ---------------- launch -----------------------------------------------------
extern "C" void kernel_launch(void* const* d_in, const int* in_sizes, int n_in,
                              void* d_out, int out_size) {
    const float* x   = (const float*)d_in[0];
    const void*  ei  = d_in[1];
    const float* W1  = (const float*)d_in[2];
    const float* as1 = (const float*)d_in[3];
    const float* ad1 = (const float*)d_in[4];
    const float* b1  = (const float*)d_in[5];
    const float* W2  = (const float*)d_in[6];
    const float* as2 = (const float*)d_in[7];
    const float* ad2 = (const float*)d_in[8];
    const float* b2  = (const float*)d_in[9];
    float*       out = (float*)d_out;

    const int N  = in_sizes[0] / 128;
    const int E  = out_size;
    const int TE = E + N;
    const int nb = (N + 255) / 256;

    // dynamic smem: buffers + s_part, in bytes
    constexpr int SM1 = (2 * 128 * 36 + 2 * 32 * (128 + 8)) * 4 + 4 * 128 * 2 * 4;
    constexpr int SM2 = (2 * 128 * 36 + 2 * 32 * (64 + 8)) * 4 + 4 * 128 * 2 * 4;
    cudaFuncSetAttribute(k_mma<128, 128, 256, 0>,
                         cudaFuncAttributeMaxDynamicSharedMemorySize, SM1);
    cudaFuncSetAttribute(k_mma<64, 256, 64, 1>,
                         cudaFuncAttributeMaxDynamicSharedMemorySize, SM2);

    // edge dtype detect + convert + hist (self-loops folded into init)
    int nwords = 2 * E < 2048 ? 2 * E : 2048;
    k_detect<<<1, 256>>>((const unsigned*)ei, nwords);
    k_init_counts<<<nb, 256>>>(N);
    k_cvt_hist<<<(E + 255) / 256, 256>>>(E, ei);

    // GEMM1 in slot 4 (ncu capture window); edge-independent so safe here
    k_mma<128, 128, 256, 0><<<dim3(2, (N + 127) / 128), 256, SM1>>>(N, x, W1, as1, ad1);

    // parallel exclusive scan -> rowptr/cursor
    k_bsum<<<nb, 256>>>(N);
    k_scan_sums<<<1, 256>>>(nb, N);
    k_scan_apply<<<nb, 256>>>(N);
    k_scatter<<<(TE + 255) / 256, 256>>>(E, N);

    // layer 1 aggregation (att logits fused into GEMM epilogue)
    k_agg1<<<N, 256>>>(b1);

    // layer 2
    k_mma<64, 256, 64, 1><<<dim3(1, (N + 127) / 128), 256, SM2>>>(N, nullptr, W2, as2, ad2);
    k_agg2<<<N, 64>>>(b2);

    // decode
    k_decode<<<(E * 32 + 255) / 256, 256>>>(E, out);
}